// round 1
// baseline (speedup 1.0000x reference)
#include <cuda_runtime.h>
#include <math.h>

// ---------------- scratch (no allocations allowed) ----------------
__device__ float g_x[512 * 256 * 400];      // conv1 output (B,256,20,20)  ~210MB
__device__ float g_u[512 * 9216];           // primary caps (B,1152,8) squashed
__device__ float g_bij[1152 * 10];          // routing logits
__device__ float g_c[1152 * 10];            // softmax coupling
__device__ float g_s[512 * 160];            // s (B,10,16)
__device__ float g_v[512 * 160];            // v (B,10,16)
__device__ int   g_best[512];
__device__ float g_h1[512 * 512];
__device__ float g_h2[512 * 1024];

// ---------------- conv1: (B,1,28,28) -> relu -> (B,256,20,20) ----------------
// grid (512, 32), block 400. Each block: one image, 8 output channels.
__global__ void conv1_kernel(const float* __restrict__ img,
                             const float* __restrict__ w,
                             const float* __restrict__ bias) {
    __shared__ float simg[784];
    __shared__ float sw[8 * 81];
    int b = blockIdx.x;
    int cg = blockIdx.y;           // channel group of 8
    int t = threadIdx.x;           // 400
    for (int i = t; i < 784; i += 400) simg[i] = img[b * 784 + i];
    for (int i = t; i < 648; i += 400) sw[i] = w[cg * 648 + i];
    __syncthreads();
    int oy = t / 20, ox = t % 20;
    float acc[8];
#pragma unroll
    for (int c = 0; c < 8; c++) acc[c] = bias[cg * 8 + c];
#pragma unroll
    for (int ky = 0; ky < 9; ky++) {
#pragma unroll
        for (int kx = 0; kx < 9; kx++) {
            float xv = simg[(oy + ky) * 28 + ox + kx];
#pragma unroll
            for (int c = 0; c < 8; c++)
                acc[c] += xv * sw[c * 81 + ky * 9 + kx];
        }
    }
#pragma unroll
    for (int c = 0; c < 8; c++)
        g_x[(b * 256 + cg * 8 + c) * 400 + t] = fmaxf(acc[c], 0.0f);
}

// ---------------- primary-caps conv as implicit GEMM ----------------
// M = 512*36 = 18432 (b,pos), N = 256 (co), K = 20736 (ci,ky,kx), stride 2.
// 128x128 tile, BK=16, 256 threads, 8x8 per thread.
__global__ void pc_gemm_kernel(const float* __restrict__ w,
                               const float* __restrict__ bias) {
    __shared__ float As[16][128];
    __shared__ float Bs[16][128];
    int tid = threadIdx.x;
    int m0 = blockIdx.x * 128;
    int n0 = blockIdx.y * 128;

    // A-load mapping: thread loads 8 consecutive m at one k_local
    int a_k = tid >> 4;            // 0..15
    int a_m = (tid & 15) * 8;      // 0..120
    int mb[8];
#pragma unroll
    for (int i = 0; i < 8; i++) {
        int m = m0 + a_m + i;
        int bb = m / 36, pos = m - bb * 36;
        mb[i] = bb * 102400 + (pos / 6) * 40 + (pos % 6) * 2;
    }
    // B-load mapping: thread loads 8 consecutive k at one co
    int b_co = tid >> 1;
    int b_ko = (tid & 1) * 8;
    const float* wrow = w + (size_t)(n0 + b_co) * 20736 + b_ko;

    int ty = tid >> 4, tx = tid & 15;
    float acc[8][8];
#pragma unroll
    for (int i = 0; i < 8; i++)
#pragma unroll
        for (int j = 0; j < 8; j++) acc[i][j] = 0.0f;

    for (int k0 = 0; k0 < 20736; k0 += 16) {
        int k = k0 + a_k;
        int ci = k / 81, rem = k - ci * 81;
        int ab = ci * 400 + (rem / 9) * 20 + (rem % 9);
#pragma unroll
        for (int i = 0; i < 8; i++) As[a_k][a_m + i] = g_x[mb[i] + ab];

        float4 v0 = *(const float4*)(wrow + k0);
        float4 v1 = *(const float4*)(wrow + k0 + 4);
        Bs[b_ko + 0][b_co] = v0.x; Bs[b_ko + 1][b_co] = v0.y;
        Bs[b_ko + 2][b_co] = v0.z; Bs[b_ko + 3][b_co] = v0.w;
        Bs[b_ko + 4][b_co] = v1.x; Bs[b_ko + 5][b_co] = v1.y;
        Bs[b_ko + 6][b_co] = v1.z; Bs[b_ko + 7][b_co] = v1.w;
        __syncthreads();

#pragma unroll
        for (int kk = 0; kk < 16; kk++) {
            float4 a0 = *(const float4*)&As[kk][ty * 8];
            float4 a1 = *(const float4*)&As[kk][ty * 8 + 4];
            float4 c0 = *(const float4*)&Bs[kk][tx * 8];
            float4 c1 = *(const float4*)&Bs[kk][tx * 8 + 4];
            float a[8] = {a0.x, a0.y, a0.z, a0.w, a1.x, a1.y, a1.z, a1.w};
            float c[8] = {c0.x, c0.y, c0.z, c0.w, c1.x, c1.y, c1.z, c1.w};
#pragma unroll
            for (int i = 0; i < 8; i++)
#pragma unroll
                for (int j = 0; j < 8; j++)
                    acc[i][j] += a[i] * c[j];
        }
        __syncthreads();
    }
    // write: u[b, co*36+pos] = acc + bias[co]
#pragma unroll
    for (int i = 0; i < 8; i++) {
        int m = m0 + ty * 8 + i;
        int bb = m / 36, pos = m - bb * 36;
        float* urow = g_u + bb * 9216 + pos;
#pragma unroll
        for (int j = 0; j < 8; j++) {
            int n = n0 + tx * 8 + j;
            urow[n * 36] = acc[i][j] + bias[n];
        }
    }
}

// ---------------- squash u (eps=1e-7), per (b,r) ----------------
__global__ void squash_u_kernel() {
    int idx = blockIdx.x * 256 + threadIdx.x;  // < 589824
    float* up = g_u + (size_t)idx * 8;
    float4 u0 = *(float4*)up;
    float4 u1 = *(float4*)(up + 4);
    float sn = 1e-7f + u0.x * u0.x + u0.y * u0.y + u0.z * u0.z + u0.w * u0.w
                     + u1.x * u1.x + u1.y * u1.y + u1.z * u1.z + u1.w * u1.w;
    float sc = sn / ((1.0f + sn) * sqrtf(sn));
    u0.x *= sc; u0.y *= sc; u0.z *= sc; u0.w *= sc;
    u1.x *= sc; u1.y *= sc; u1.z *= sc; u1.w *= sc;
    *(float4*)up = u0;
    *(float4*)(up + 4) = u1;
}

__global__ void zero_bij_kernel() {
    int i = blockIdx.x * 256 + threadIdx.x;
    if (i < 11520) g_bij[i] = 0.0f;
}

// softmax over routes (axis 0), one block per k
__global__ void softmax_c_kernel() {
    int k = blockIdx.x;
    int tid = threadIdx.x;
    __shared__ float red[256];
    float m = -1e30f;
    for (int r = tid; r < 1152; r += 256) m = fmaxf(m, g_bij[r * 10 + k]);
    red[tid] = m; __syncthreads();
    for (int s = 128; s; s >>= 1) { if (tid < s) red[tid] = fmaxf(red[tid], red[tid + s]); __syncthreads(); }
    m = red[0]; __syncthreads();
    float sum = 0.0f;
    for (int r = tid; r < 1152; r += 256) sum += expf(g_bij[r * 10 + k] - m);
    red[tid] = sum; __syncthreads();
    for (int s = 128; s; s >>= 1) { if (tid < s) red[tid] += red[tid + s]; __syncthreads(); }
    sum = red[0];
    float inv = 1.0f / sum;
    for (int r = tid; r < 1152; r += 256)
        g_c[r * 10 + k] = expf(g_bij[r * 10 + k] - m) * inv;
}

// s[b,k,o] = sum_r c[r,k] * dot8(W[r,k,o,:], u[b,r,:]) — fused u_hat
// grid 128 (b-tile of 4), 160 threads = (k,o). dyn smem 4*9216 floats.
__global__ void s_kernel(const float* __restrict__ W) {
    extern __shared__ float su[];
    int tid = threadIdx.x;
    int b0 = blockIdx.x * 4;
    const float4* src = (const float4*)(g_u + (size_t)b0 * 9216);
    for (int i = tid; i < 9216; i += 160) ((float4*)su)[i] = src[i];
    __syncthreads();
    int k = tid / 16;
    const float* wp = W + tid * 8;     // (k*16+o)*8
    float acc0 = 0, acc1 = 0, acc2 = 0, acc3 = 0;
    for (int r = 0; r < 1152; r++) {
        float4 w0 = *(const float4*)(wp + r * 1280);
        float4 w1 = *(const float4*)(wp + r * 1280 + 4);
        float cv = g_c[r * 10 + k];
        const float* u0 = su + r * 8;
        const float* u1 = u0 + 9216;
        const float* u2 = u0 + 18432;
        const float* u3 = u0 + 27648;
        float d0 = w0.x*u0[0]+w0.y*u0[1]+w0.z*u0[2]+w0.w*u0[3]+w1.x*u0[4]+w1.y*u0[5]+w1.z*u0[6]+w1.w*u0[7];
        float d1 = w0.x*u1[0]+w0.y*u1[1]+w0.z*u1[2]+w0.w*u1[3]+w1.x*u1[4]+w1.y*u1[5]+w1.z*u1[6]+w1.w*u1[7];
        float d2 = w0.x*u2[0]+w0.y*u2[1]+w0.z*u2[2]+w0.w*u2[3]+w1.x*u2[4]+w1.y*u2[5]+w1.z*u2[6]+w1.w*u2[7];
        float d3 = w0.x*u3[0]+w0.y*u3[1]+w0.z*u3[2]+w0.w*u3[3]+w1.x*u3[4]+w1.y*u3[5]+w1.z*u3[6]+w1.w*u3[7];
        acc0 += cv * d0; acc1 += cv * d1; acc2 += cv * d2; acc3 += cv * d3;
    }
    g_s[(b0 + 0) * 160 + tid] = acc0;
    g_s[(b0 + 1) * 160 + tid] = acc1;
    g_s[(b0 + 2) * 160 + tid] = acc2;
    g_s[(b0 + 3) * 160 + tid] = acc3;
}

// v = squash(s, eps=0): per (b,k)
__global__ void vsquash_kernel() {
    int idx = blockIdx.x * 256 + threadIdx.x;  // < 5120
    const float* sp = g_s + (size_t)idx * 16;
    float sn = 0.0f;
#pragma unroll
    for (int o = 0; o < 16; o++) sn += sp[o] * sp[o];
    float sc = sn / ((1.0f + sn) * sqrtf(sn));
    float* vp = g_v + (size_t)idx * 16;
#pragma unroll
    for (int o = 0; o < 16; o++) vp[o] = sp[o] * sc;
}

// b_ij[r,k] += (1/B) sum_b sum_c u[b,r,c] * (sum_o W[r,k,o,c]*v[b,k,o])
// grid 1152 (r), 320 threads = (k=tid/32, lane over b)
__global__ void agree_kernel(const float* __restrict__ W) {
    int r = blockIdx.x;
    int tid = threadIdx.x;
    __shared__ float sw[1280];
    for (int i = tid; i < 1280; i += 320) sw[i] = W[r * 1280 + i];
    __syncthreads();
    int k = tid >> 5, lane = tid & 31;
    const float* swk = sw + k * 128;
    float acc = 0.0f;
    for (int b = lane; b < 512; b += 32) {
        const float* vb = g_v + b * 160 + k * 16;
        float p[8] = {0, 0, 0, 0, 0, 0, 0, 0};
#pragma unroll
        for (int o = 0; o < 16; o++) {
            float vv = vb[o];
            const float* wo = swk + o * 8;
#pragma unroll
            for (int c = 0; c < 8; c++) p[c] += wo[c] * vv;
        }
        const float* ub = g_u + (size_t)b * 9216 + r * 8;
        float d = 0.0f;
#pragma unroll
        for (int c = 0; c < 8; c++) d += p[c] * ub[c];
        acc += d;
    }
#pragma unroll
    for (int off = 16; off; off >>= 1) acc += __shfl_down_sync(0xffffffffu, acc, off);
    if (lane == 0) g_bij[r * 10 + k] += acc * (1.0f / 512.0f);
}

// argmax over capsule norms + write mask + copy obj_vectors. grid 512, 32 threads.
__global__ void mask_kernel(float* __restrict__ out_obj, float* __restrict__ out_mask) {
    int b = blockIdx.x;
    int lane = threadIdx.x;
    const float* vb = g_v + b * 160;
    float sn = -1.0f; int idx = 1000;
    if (lane < 10) {
        sn = 0.0f;
#pragma unroll
        for (int o = 0; o < 16; o++) { float x = vb[lane * 16 + o]; sn += x * x; }
        idx = lane;
    }
#pragma unroll
    for (int off = 16; off; off >>= 1) {
        float osn = __shfl_down_sync(0xffffffffu, sn, off);
        int oidx = __shfl_down_sync(0xffffffffu, idx, off);
        if (osn > sn || (osn == sn && oidx < idx)) { sn = osn; idx = oidx; }
    }
    int best = __shfl_sync(0xffffffffu, idx, 0);
    if (lane == 0) g_best[b] = best;
    if (lane < 10) out_mask[b * 10 + lane] = (lane == best) ? 1.0f : 0.0f;
    for (int i = lane; i < 160; i += 32) out_obj[b * 160 + i] = vb[i];
}

// h1[b,j] = relu(b1[j] + sum_o v[b,best,o]*w1[(best*16+o)*512+j]) — exploits one-hot mask
__global__ void h1_kernel(const float* __restrict__ w1, const float* __restrict__ b1) {
    int b = blockIdx.x;
    int j = threadIdx.x;  // 512
    __shared__ float sv[16];
    __shared__ int sb;
    if (j == 0) sb = g_best[b];
    __syncthreads();
    if (j < 16) sv[j] = g_v[b * 160 + sb * 16 + j];
    __syncthreads();
    float acc = b1[j];
    const float* wbase = w1 + (size_t)sb * 16 * 512 + j;
#pragma unroll
    for (int o = 0; o < 16; o++) acc += sv[o] * wbase[o * 512];
    g_h1[b * 512 + j] = fmaxf(acc, 0.0f);
}

// generic tiled GEMM: C[M,N] = act(A[M,K] @ W[K,N] + bias). 64x64x16, 256 thr, 4x4.
// ACT: 1 = relu, 2 = sigmoid. M%64==0, K%16==0 assumed; N guarded.
template <int ACT>
__global__ void gemm_kernel(const float* __restrict__ A, const float* __restrict__ W,
                            const float* __restrict__ bias, float* __restrict__ C,
                            int M, int N, int K) {
    __shared__ float As[16][65];
    __shared__ float Bs[16][64];
    int tid = threadIdx.x;
    int m0 = blockIdx.x * 64, n0 = blockIdx.y * 64;
    int tx = tid & 15, ty = tid >> 4;
    float acc[4][4];
#pragma unroll
    for (int i = 0; i < 4; i++)
#pragma unroll
        for (int j = 0; j < 4; j++) acc[i][j] = 0.0f;

    int arow = tid >> 2, akc = (tid & 3) * 4;
    int bkr = tid >> 4, bnc = (tid & 15) * 4;

    for (int k0 = 0; k0 < K; k0 += 16) {
        float4 av = *(const float4*)(A + (size_t)(m0 + arow) * K + k0 + akc);
        As[akc + 0][arow] = av.x; As[akc + 1][arow] = av.y;
        As[akc + 2][arow] = av.z; As[akc + 3][arow] = av.w;
#pragma unroll
        for (int i = 0; i < 4; i++) {
            int n = n0 + bnc + i;
            Bs[bkr][bnc + i] = (n < N) ? W[(size_t)(k0 + bkr) * N + n] : 0.0f;
        }
        __syncthreads();
#pragma unroll
        for (int kk = 0; kk < 16; kk++) {
            float a[4], bb[4];
#pragma unroll
            for (int i = 0; i < 4; i++) a[i] = As[kk][ty * 4 + i];
            float4 bv = *(const float4*)&Bs[kk][tx * 4];
            bb[0] = bv.x; bb[1] = bv.y; bb[2] = bv.z; bb[3] = bv.w;
#pragma unroll
            for (int i = 0; i < 4; i++)
#pragma unroll
                for (int j = 0; j < 4; j++) acc[i][j] += a[i] * bb[j];
        }
        __syncthreads();
    }
#pragma unroll
    for (int i = 0; i < 4; i++) {
        int m = m0 + ty * 4 + i;
#pragma unroll
        for (int j = 0; j < 4; j++) {
            int n = n0 + tx * 4 + j;
            if (n < N) {
                float v = acc[i][j] + bias[n];
                if (ACT == 1) v = fmaxf(v, 0.0f);
                else if (ACT == 2) v = 1.0f / (1.0f + expf(-v));
                C[(size_t)m * N + n] = v;
            }
        }
    }
}

extern "C" void kernel_launch(void* const* d_in, const int* in_sizes, int n_in,
                              void* d_out, int out_size) {
    const float* image  = (const float*)d_in[0];
    const float* conv_w = (const float*)d_in[1];
    const float* conv_b = (const float*)d_in[2];
    const float* pc_w   = (const float*)d_in[3];
    const float* pc_b   = (const float*)d_in[4];
    const float* W_obj  = (const float*)d_in[5];
    const float* dec_w1 = (const float*)d_in[6];
    const float* dec_b1 = (const float*)d_in[7];
    const float* dec_w2 = (const float*)d_in[8];
    const float* dec_b2 = (const float*)d_in[9];
    const float* dec_w3 = (const float*)d_in[10];
    const float* dec_b3 = (const float*)d_in[11];

    float* out = (float*)d_out;
    float* out_obj  = out;                 // 512*160
    float* out_rec  = out + 81920;         // 512*784
    float* out_mask = out + 483328;        // 512*10

    cudaFuncSetAttribute(s_kernel, cudaFuncAttributeMaxDynamicSharedMemorySize, 4 * 9216 * 4);

    void *ph1 = nullptr, *ph2 = nullptr;
    cudaGetSymbolAddress(&ph1, g_h1);
    cudaGetSymbolAddress(&ph2, g_h2);

    conv1_kernel<<<dim3(512, 32), 400>>>(image, conv_w, conv_b);
    pc_gemm_kernel<<<dim3(144, 2), 256>>>(pc_w, pc_b);
    squash_u_kernel<<<2304, 256>>>();
    zero_bij_kernel<<<45, 256>>>();

    for (int it = 0; it < 3; it++) {
        softmax_c_kernel<<<10, 256>>>();
        s_kernel<<<128, 160, 4 * 9216 * 4>>>(W_obj);
        vsquash_kernel<<<20, 256>>>();
        if (it < 2) agree_kernel<<<1152, 320>>>(W_obj);
    }

    mask_kernel<<<512, 32>>>(out_obj, out_mask);
    h1_kernel<<<512, 512>>>(dec_w1, dec_b1);
    gemm_kernel<1><<<dim3(8, 16), 256>>>((const float*)ph1, dec_w2, dec_b2, (float*)ph2, 512, 1024, 512);
    gemm_kernel<2><<<dim3(8, 13), 256>>>((const float*)ph2, dec_w3, dec_b3, out_rec, 512, 784, 1024);
}

// round 4
// speedup vs baseline: 1.5745x; 1.5745x over previous
#include <cuda_runtime.h>
#include <cuda_bf16.h>
#include <stdint.h>
#include <math.h>

// ==================== scratch (device globals; no allocations) ====================
__device__ uint4 g_xhi4[6553600];          // conv1 out hi bf16: [256*400 k-rows][512 b]
__device__ uint4 g_xlo4[6553600];          // conv1 out lo bf16
__device__ uint4 g_whi4[663552];           // pc_w hi bf16: [256 co][20736 k]
__device__ uint4 g_wlo4[663552];           // pc_w lo bf16
__device__ float g_imgt[784 * 512];        // transposed image [pix][b]
__device__ float g_u[512 * 9216];          // primary caps (B,1152,8), then squashed
__device__ float g_bij[1152 * 10];
__device__ float g_c[1152 * 10];
__device__ float g_wsc[9216 * 160];        // c-scaled routing weights [rc][(k,o)]
__device__ float g_zero160[160];
__device__ float g_s[512 * 160];
__device__ float g_v[512 * 160];
__device__ int   g_best[512];
__device__ float g_h1[512 * 512];
__device__ float g_h2[512 * 1024];

// ==================== helpers ====================
__device__ __forceinline__ uint32_t smem_to_u32(const void* p) {
    uint32_t a;
    asm("{ .reg .u64 t; cvta.to.shared.u64 t, %1; cvt.u32.u64 %0, t; }" : "=r"(a) : "l"(p));
    return a;
}
#define CP16(dst, src) \
    asm volatile("cp.async.cg.shared.global [%0], [%1], 16;" :: "r"(dst), "l"(src))
#define CP_COMMIT() asm volatile("cp.async.commit_group;" ::: "memory")
#define CP_WAIT1()  asm volatile("cp.async.wait_group 1;" ::: "memory")
#define LDSM(r, addr) \
    asm volatile("ldmatrix.sync.aligned.m8n8.x4.shared.b16 {%0,%1,%2,%3}, [%4];" \
        : "=r"((r)[0]), "=r"((r)[1]), "=r"((r)[2]), "=r"((r)[3]) : "r"(addr))
#define LDSM_T(r, addr) \
    asm volatile("ldmatrix.sync.aligned.m8n8.x4.trans.shared.b16 {%0,%1,%2,%3}, [%4];" \
        : "=r"((r)[0]), "=r"((r)[1]), "=r"((r)[2]), "=r"((r)[3]) : "r"(addr))
#define MMA_BF16(d, a, b0, b1) \
    asm volatile("mma.sync.aligned.m16n8k16.row.col.f32.bf16.bf16.f32 " \
        "{%0,%1,%2,%3}, {%4,%5,%6,%7}, {%8,%9}, {%0,%1,%2,%3};" \
        : "+f"((d)[0]), "+f"((d)[1]), "+f"((d)[2]), "+f"((d)[3]) \
        : "r"((a)[0]), "r"((a)[1]), "r"((a)[2]), "r"((a)[3]), "r"(b0), "r"(b1))

__device__ __forceinline__ void splitf(float v, unsigned short& h, unsigned short& l) {
    __nv_bfloat16 hb = __float2bfloat16(v);
    float r = v - __bfloat162float(hb);
    __nv_bfloat16 lb = __float2bfloat16(r);
    h = __bfloat16_as_ushort(hb);
    l = __bfloat16_as_ushort(lb);
}

// ==================== image transpose (512,784) -> (784,512) ====================
__global__ void transpose_img_kernel(const float* __restrict__ img) {
    __shared__ float t[32][33];
    int tx = threadIdx.x, ty = threadIdx.y;   // 32 x 8
    int p0 = blockIdx.x * 32, b0 = blockIdx.y * 32;
#pragma unroll
    for (int i = 0; i < 4; i++) {
        int p = p0 + tx, b = b0 + ty + i * 8;
        if (p < 784) t[ty + i * 8][tx] = img[b * 784 + p];
    }
    __syncthreads();
#pragma unroll
    for (int i = 0; i < 4; i++) {
        int p = p0 + ty + i * 8, b = b0 + tx;
        if (p < 784) g_imgt[p * 512 + b] = t[tx][ty + i * 8];
    }
}

// ==================== conv1: b-major, writes bf16 hi/lo split ====================
// grid (400 pos, 32 cgroups-of-8), block 128 (b); each thread handles 4 b.
__global__ void conv1_t_kernel(const float* __restrict__ w,
                               const float* __restrict__ bias) {
    __shared__ float sw[648];
    int pos = blockIdx.x, cg = blockIdx.y, tid = threadIdx.x;
    for (int i = tid; i < 648; i += 128) sw[i] = w[cg * 648 + i];
    __syncthreads();
    int oy = pos / 20, ox = pos % 20;
    float acc[4][8];
#pragma unroll
    for (int c = 0; c < 8; c++) {
        float bv = bias[cg * 8 + c];
#pragma unroll
        for (int q = 0; q < 4; q++) acc[q][c] = bv;
    }
    for (int ky = 0; ky < 9; ky++) {
#pragma unroll
        for (int kx = 0; kx < 9; kx++) {
            const float* ip = g_imgt + ((oy + ky) * 28 + ox + kx) * 512 + tid;
            float x0 = ip[0], x1 = ip[128], x2 = ip[256], x3 = ip[384];
#pragma unroll
            for (int c = 0; c < 8; c++) {
                float wv = sw[c * 81 + ky * 9 + kx];
                acc[0][c] += x0 * wv; acc[1][c] += x1 * wv;
                acc[2][c] += x2 * wv; acc[3][c] += x3 * wv;
            }
        }
    }
    unsigned short* xhi = (unsigned short*)g_xhi4;
    unsigned short* xlo = (unsigned short*)g_xlo4;
#pragma unroll
    for (int c = 0; c < 8; c++) {
        size_t row = (size_t)(cg * 8 + c) * 400 + pos;
#pragma unroll
        for (int q = 0; q < 4; q++) {
            float v = fmaxf(acc[q][c], 0.0f);
            unsigned short h, l;
            splitf(v, h, l);
            xhi[row * 512 + tid + q * 128] = h;
            xlo[row * 512 + tid + q * 128] = l;
        }
    }
}

// ==================== weight split pc_w -> bf16 hi/lo ====================
__global__ void wsplit_kernel(const float* __restrict__ w) {
    int idx = blockIdx.x * 256 + threadIdx.x;
    if (idx < 5308416) {
        unsigned short h, l;
        splitf(w[idx], h, l);
        ((unsigned short*)g_whi4)[idx] = h;
        ((unsigned short*)g_wlo4)[idx] = l;
    }
}

// ==================== primary-caps conv: mma.sync bf16 3-pass implicit GEMM ======
// grid (36 pos, 4 btile, 2 nhalf), block 256 (8 warps, 4m x 2n).
// CTA tile: M=128 (b) x N=128 (co). K=20736 in BK=32 chunks, double-buffered.
// smem per buffer (32KB): A_hi[32k][128m] 8K | A_lo 8K | B_hi[128n][32k] 8K | B_lo 8K
__device__ __forceinline__ int rowOf(int k, int oy2, int ox2) {
    int ci = k / 81;
    int rem = k - ci * 81;
    int ky = rem / 9;
    int kx = rem - ky * 9;
    return ci * 400 + (oy2 + ky) * 20 + (ox2 + kx);
}

__device__ __forceinline__ void pc_fill(int chunk, uint32_t sbuf,
                                        const unsigned short* xhi, const unsigned short* xlo,
                                        const unsigned short* whi, const unsigned short* wlo,
                                        int bbase, int n0, int oy2, int ox2, int tid) {
    // A: 32 k-rows x 128 m bf16 (256B/row), hi+lo. thread: m-group g, k rows kA, kA+16.
    int g = tid & 15, kA = tid >> 4;            // g:0..15 (8 m each), kA:0..15
    int k0 = chunk * 32 + kA;
    int r0 = rowOf(k0, oy2, ox2);
    int r1 = rowOf(k0 + 16, oy2, ox2);
    size_t s0 = (size_t)r0 * 512 + bbase + g * 8;
    size_t s1 = (size_t)r1 * 512 + bbase + g * 8;
    uint32_t sw = (uint32_t)((g ^ (kA & 7)) << 4);
    uint32_t d0 = sbuf + kA * 256 + sw;
    uint32_t d1 = sbuf + (kA + 16) * 256 + sw;
    CP16(d0, xhi + s0);
    CP16(d1, xhi + s1);
    CP16(d0 + 8192, xlo + s0);
    CP16(d1 + 8192, xlo + s1);
    // B: 128 n-rows x 32 k bf16 (64B/row), hi+lo. thread: n rows nB, nB+64; 16B seg q.
    int q = tid & 3, nB = tid >> 2;             // nB:0..63
    size_t t0 = (size_t)(n0 + nB) * 20736 + chunk * 32 + q * 8;
    size_t t1 = t0 + (size_t)64 * 20736;
    uint32_t swb0 = (uint32_t)((q ^ ((nB >> 1) & 3)) << 4);
    uint32_t swb1 = (uint32_t)((q ^ (((nB + 64) >> 1) & 3)) << 4);
    uint32_t e0 = sbuf + 16384 + nB * 64 + swb0;
    uint32_t e1 = sbuf + 16384 + (nB + 64) * 64 + swb1;
    CP16(e0, whi + t0);
    CP16(e1, whi + t1);
    CP16(e0 + 8192, wlo + t0);
    CP16(e1 + 8192, wlo + t1);
}

__device__ __forceinline__ void pc_compute(uint32_t sbuf, int wm, int wn, int lane,
                                           float acc[2][8][4]) {
#pragma unroll
    for (int kt = 0; kt < 2; kt++) {
        int lrow = lane & 7, msel = (lane >> 3) & 1, ksel = (lane >> 4) & 1;
        int kl = kt * 16 + lrow + ksel * 8;
        uint32_t a[2][2][4];
#pragma unroll
        for (int mt = 0; mt < 2; mt++) {
            int mo = wm + mt * 16 + msel * 8;
            uint32_t addr = sbuf + kl * 256 + (uint32_t)((((mo >> 3) ^ (kl & 7))) << 4);
            LDSM_T(a[0][mt], addr);
            LDSM_T(a[1][mt], addr + 8192);
        }
        uint32_t bb[2][4][4];
        int nsel = (lane >> 4) & 1, qsel = (lane >> 3) & 1;
        int q = kt * 2 + qsel;
#pragma unroll
        for (int p = 0; p < 4; p++) {
            int nloc = wn + p * 16 + nsel * 8 + (lane & 7);
            uint32_t addr = sbuf + 16384 + nloc * 64 +
                            (uint32_t)((q ^ ((nloc >> 1) & 3)) << 4);
            LDSM(bb[0][p], addr);
            LDSM(bb[1][p], addr + 8192);
        }
#pragma unroll
        for (int mt = 0; mt < 2; mt++)
#pragma unroll
            for (int p = 0; p < 4; p++)
#pragma unroll
                for (int s = 0; s < 2; s++) {
                    int nt = p * 2 + s;
                    MMA_BF16(acc[mt][nt], a[0][mt], bb[0][p][2 * s], bb[0][p][2 * s + 1]);
                    MMA_BF16(acc[mt][nt], a[0][mt], bb[1][p][2 * s], bb[1][p][2 * s + 1]);
                    MMA_BF16(acc[mt][nt], a[1][mt], bb[0][p][2 * s], bb[0][p][2 * s + 1]);
                }
    }
}

__global__ __launch_bounds__(256, 1) void pc_mma_kernel(const float* __restrict__ pc_b) {
    extern __shared__ char smem[];
    uint32_t sb = smem_to_u32(smem);
    int tid = threadIdx.x, wid = tid >> 5, lane = tid & 31;
    int pos = blockIdx.x;
    int bbase = blockIdx.y * 128;
    int n0 = blockIdx.z * 128;
    int oy2 = (pos / 6) * 2, ox2 = (pos % 6) * 2;
    int wm = (wid >> 1) * 32, wn = (wid & 1) * 64;

    const unsigned short* xhi = (const unsigned short*)g_xhi4;
    const unsigned short* xlo = (const unsigned short*)g_xlo4;
    const unsigned short* whi = (const unsigned short*)g_whi4;
    const unsigned short* wlo = (const unsigned short*)g_wlo4;

    float acc[2][8][4];
#pragma unroll
    for (int i = 0; i < 2; i++)
#pragma unroll
        for (int j = 0; j < 8; j++)
#pragma unroll
            for (int c = 0; c < 4; c++) acc[i][j][c] = 0.0f;

    pc_fill(0, sb, xhi, xlo, whi, wlo, bbase, n0, oy2, ox2, tid);
    CP_COMMIT();
    pc_fill(1, sb + 32768, xhi, xlo, whi, wlo, bbase, n0, oy2, ox2, tid);
    CP_COMMIT();

    for (int c = 0; c < 648; c++) {
        CP_WAIT1();
        __syncthreads();
        uint32_t sbuf = sb + (c & 1) * 32768;
        pc_compute(sbuf, wm, wn, lane, acc);
        __syncthreads();
        if (c + 2 < 648)
            pc_fill(c + 2, sbuf, xhi, xlo, whi, wlo, bbase, n0, oy2, ox2, tid);
        CP_COMMIT();
    }

    // epilogue: u[b, n*36+pos] = acc + pc_b[n]
    int r0 = lane >> 2, c0 = (lane & 3) * 2;
#pragma unroll
    for (int mt = 0; mt < 2; mt++) {
        int b = bbase + wm + mt * 16 + r0;
        float* up0 = g_u + (size_t)b * 9216 + pos;
        float* up1 = up0 + (size_t)8 * 9216;
#pragma unroll
        for (int nt = 0; nt < 8; nt++) {
            int n = n0 + wn + nt * 8 + c0;
            float bv0 = __ldg(pc_b + n), bv1 = __ldg(pc_b + n + 1);
            up0[n * 36]       = acc[mt][nt][0] + bv0;
            up0[(n + 1) * 36] = acc[mt][nt][1] + bv1;
            up1[n * 36]       = acc[mt][nt][2] + bv0;
            up1[(n + 1) * 36] = acc[mt][nt][3] + bv1;
        }
    }
}

// ==================== squash u (eps=1e-7), per (b,r) ====================
__global__ void squash_u_kernel() {
    int idx = blockIdx.x * 256 + threadIdx.x;  // < 589824
    float* up = g_u + (size_t)idx * 8;
    float4 u0 = *(float4*)up;
    float4 u1 = *(float4*)(up + 4);
    float sn = 1e-7f + u0.x * u0.x + u0.y * u0.y + u0.z * u0.z + u0.w * u0.w
                     + u1.x * u1.x + u1.y * u1.y + u1.z * u1.z + u1.w * u1.w;
    float sc = sn / ((1.0f + sn) * sqrtf(sn));
    u0.x *= sc; u0.y *= sc; u0.z *= sc; u0.w *= sc;
    u1.x *= sc; u1.y *= sc; u1.z *= sc; u1.w *= sc;
    *(float4*)up = u0;
    *(float4*)(up + 4) = u1;
}

__global__ void zero_bij_kernel() {
    int i = blockIdx.x * 256 + threadIdx.x;
    if (i < 11520) g_bij[i] = 0.0f;
}

__global__ void zero160_kernel() {
    int i = threadIdx.x;
    if (i < 160) g_zero160[i] = 0.0f;
}

// softmax over routes (axis 0), one block per k
__global__ void softmax_c_kernel() {
    int k = blockIdx.x;
    int tid = threadIdx.x;
    __shared__ float red[256];
    float m = -1e30f;
    for (int r = tid; r < 1152; r += 256) m = fmaxf(m, g_bij[r * 10 + k]);
    red[tid] = m; __syncthreads();
    for (int s = 128; s; s >>= 1) { if (tid < s) red[tid] = fmaxf(red[tid], red[tid + s]); __syncthreads(); }
    m = red[0]; __syncthreads();
    float sum = 0.0f;
    for (int r = tid; r < 1152; r += 256) sum += expf(g_bij[r * 10 + k] - m);
    red[tid] = sum; __syncthreads();
    for (int s = 128; s; s >>= 1) { if (tid < s) red[tid] += red[tid + s]; __syncthreads(); }
    sum = red[0];
    float inv = 1.0f / sum;
    for (int r = tid; r < 1152; r += 256)
        g_c[r * 10 + k] = expf(g_bij[r * 10 + k] - m) * inv;
}

// g_wsc[(r*8+c)*160 + k*16+o] = W_obj[r,k,o,c] * c[r,k]
__global__ void scale_w_kernel(const float* __restrict__ W) {
    int idx = blockIdx.x * 256 + threadIdx.x;
    if (idx < 1474560) {
        int r = idx / 1280;
        int rem = idx - r * 1280;
        int k = rem >> 7;
        int oc = rem & 127;
        int o = oc >> 3;
        int c = oc & 7;
        g_wsc[(r * 8 + c) * 160 + k * 16 + o] = W[idx] * g_c[r * 10 + k];
    }
}

// v = squash(s, eps=0): per (b,k)
__global__ void vsquash_kernel() {
    int idx = blockIdx.x * 256 + threadIdx.x;  // < 5120
    const float* sp = g_s + (size_t)idx * 16;
    float sn = 0.0f;
#pragma unroll
    for (int o = 0; o < 16; o++) sn += sp[o] * sp[o];
    float sc = sn / ((1.0f + sn) * sqrtf(sn));
    float* vp = g_v + (size_t)idx * 16;
#pragma unroll
    for (int o = 0; o < 16; o++) vp[o] = sp[o] * sc;
}

// b_ij[r,k] += (1/B) sum_b sum_c u[b,r,c] * (sum_o W[r,k,o,c]*v[b,k,o])
__global__ void agree_kernel(const float* __restrict__ W) {
    int r = blockIdx.x;
    int tid = threadIdx.x;
    __shared__ float sw[1280];
    for (int i = tid; i < 1280; i += 320) sw[i] = W[r * 1280 + i];
    __syncthreads();
    int k = tid >> 5, lane = tid & 31;
    const float* swk = sw + k * 128;
    float acc = 0.0f;
    for (int b = lane; b < 512; b += 32) {
        const float* vb = g_v + b * 160 + k * 16;
        float p[8] = {0, 0, 0, 0, 0, 0, 0, 0};
#pragma unroll
        for (int o = 0; o < 16; o++) {
            float vv = vb[o];
            const float* wo = swk + o * 8;
#pragma unroll
            for (int c = 0; c < 8; c++) p[c] += wo[c] * vv;
        }
        const float* ub = g_u + (size_t)b * 9216 + r * 8;
        float d = 0.0f;
#pragma unroll
        for (int c = 0; c < 8; c++) d += p[c] * ub[c];
        acc += d;
    }
#pragma unroll
    for (int off = 16; off; off >>= 1) acc += __shfl_down_sync(0xffffffffu, acc, off);
    if (lane == 0) g_bij[r * 10 + k] += acc * (1.0f / 512.0f);
}

// argmax over capsule norms + write mask + copy obj_vectors
__global__ void mask_kernel(float* __restrict__ out_obj, float* __restrict__ out_mask) {
    int b = blockIdx.x;
    int lane = threadIdx.x;
    const float* vb = g_v + b * 160;
    float sn = -1.0f; int idx = 1000;
    if (lane < 10) {
        sn = 0.0f;
#pragma unroll
        for (int o = 0; o < 16; o++) { float x = vb[lane * 16 + o]; sn += x * x; }
        idx = lane;
    }
#pragma unroll
    for (int off = 16; off; off >>= 1) {
        float osn = __shfl_down_sync(0xffffffffu, sn, off);
        int oidx = __shfl_down_sync(0xffffffffu, idx, off);
        if (osn > sn || (osn == sn && oidx < idx)) { sn = osn; idx = oidx; }
    }
    int best = __shfl_sync(0xffffffffu, idx, 0);
    if (lane == 0) g_best[b] = best;
    if (lane < 10) out_mask[b * 10 + lane] = (lane == best) ? 1.0f : 0.0f;
    for (int i = lane; i < 160; i += 32) out_obj[b * 160 + i] = vb[i];
}

// h1[b,j] = relu(b1[j] + sum_o v[b,best,o]*w1[(best*16+o)*512+j])
__global__ void h1_kernel(const float* __restrict__ w1, const float* __restrict__ b1) {
    int b = blockIdx.x;
    int j = threadIdx.x;  // 512
    __shared__ float sv[16];
    __shared__ int sbest;
    if (j == 0) sbest = g_best[b];
    __syncthreads();
    if (j < 16) sv[j] = g_v[b * 160 + sbest * 16 + j];
    __syncthreads();
    float acc = b1[j];
    const float* wbase = w1 + (size_t)sbest * 16 * 512 + j;
#pragma unroll
    for (int o = 0; o < 16; o++) acc += sv[o] * wbase[o * 512];
    g_h1[b * 512 + j] = fmaxf(acc, 0.0f);
}

// generic tiled GEMM: C = act(A[M,K] @ W[K,N] + bias). 64x64x16, 256 thr, 4x4.
// ACT: 0 = none, 1 = relu, 2 = sigmoid. M%64==0, K%16==0; N guarded.
template <int ACT>
__global__ void gemm_kernel(const float* __restrict__ A, const float* __restrict__ W,
                            const float* __restrict__ bias, float* __restrict__ C,
                            int M, int N, int K) {
    __shared__ float As[16][65];
    __shared__ float Bs[16][64];
    int tid = threadIdx.x;
    int m0 = blockIdx.x * 64, n0 = blockIdx.y * 64;
    int tx = tid & 15, ty = tid >> 4;
    float acc[4][4];
#pragma unroll
    for (int i = 0; i < 4; i++)
#pragma unroll
        for (int j = 0; j < 4; j++) acc[i][j] = 0.0f;

    int arow = tid >> 2, akc = (tid & 3) * 4;
    int bkr = tid >> 4, bnc = (tid & 15) * 4;

    for (int k0 = 0; k0 < K; k0 += 16) {
        float4 av = *(const float4*)(A + (size_t)(m0 + arow) * K + k0 + akc);
        As[akc + 0][arow] = av.x; As[akc + 1][arow] = av.y;
        As[akc + 2][arow] = av.z; As[akc + 3][arow] = av.w;
#pragma unroll
        for (int i = 0; i < 4; i++) {
            int n = n0 + bnc + i;
            Bs[bkr][bnc + i] = (n < N) ? W[(size_t)(k0 + bkr) * N + n] : 0.0f;
        }
        __syncthreads();
#pragma unroll
        for (int kk = 0; kk < 16; kk++) {
            float a[4], bb[4];
#pragma unroll
            for (int i = 0; i < 4; i++) a[i] = As[kk][ty * 4 + i];
            float4 bv = *(const float4*)&Bs[kk][tx * 4];
            bb[0] = bv.x; bb[1] = bv.y; bb[2] = bv.z; bb[3] = bv.w;
#pragma unroll
            for (int i = 0; i < 4; i++)
#pragma unroll
                for (int j = 0; j < 4; j++) acc[i][j] += a[i] * bb[j];
        }
        __syncthreads();
    }
#pragma unroll
    for (int i = 0; i < 4; i++) {
        int m = m0 + ty * 4 + i;
#pragma unroll
        for (int j = 0; j < 4; j++) {
            int n = n0 + tx * 4 + j;
            if (n < N) {
                float v = acc[i][j] + bias[n];
                if (ACT == 1) v = fmaxf(v, 0.0f);
                else if (ACT == 2) v = 1.0f / (1.0f + expf(-v));
                C[(size_t)m * N + n] = v;
            }
        }
    }
}

extern "C" void kernel_launch(void* const* d_in, const int* in_sizes, int n_in,
                              void* d_out, int out_size) {
    const float* image  = (const float*)d_in[0];
    const float* conv_w = (const float*)d_in[1];
    const float* conv_b = (const float*)d_in[2];
    const float* pc_w   = (const float*)d_in[3];
    const float* pc_b   = (const float*)d_in[4];
    const float* W_obj  = (const float*)d_in[5];
    const float* dec_w1 = (const float*)d_in[6];
    const float* dec_b1 = (const float*)d_in[7];
    const float* dec_w2 = (const float*)d_in[8];
    const float* dec_b2 = (const float*)d_in[9];
    const float* dec_w3 = (const float*)d_in[10];
    const float* dec_b3 = (const float*)d_in[11];

    float* out = (float*)d_out;
    float* out_obj  = out;                 // 512*160
    float* out_rec  = out + 81920;         // 512*784
    float* out_mask = out + 483328;        // 512*10

    cudaFuncSetAttribute(pc_mma_kernel, cudaFuncAttributeMaxDynamicSharedMemorySize, 65536);

    void *pu = nullptr, *pwsc = nullptr, *pz = nullptr, *ps = nullptr;
    void *ph1 = nullptr, *ph2 = nullptr;
    cudaGetSymbolAddress(&pu, g_u);
    cudaGetSymbolAddress(&pwsc, g_wsc);
    cudaGetSymbolAddress(&pz, g_zero160);
    cudaGetSymbolAddress(&ps, g_s);
    cudaGetSymbolAddress(&ph1, g_h1);
    cudaGetSymbolAddress(&ph2, g_h2);

    // launch order chosen so ncu (-s 5 -c 1) profiles pc_mma_kernel (launch #6)
    transpose_img_kernel<<<dim3(25, 16), dim3(32, 8)>>>(image);   // 1
    wsplit_kernel<<<20736, 256>>>(pc_w);                          // 2
    zero_bij_kernel<<<45, 256>>>();                               // 3
    conv1_t_kernel<<<dim3(400, 32), 128>>>(conv_w, conv_b);       // 4
    zero160_kernel<<<1, 160>>>();                                 // 5
    pc_mma_kernel<<<dim3(36, 4, 2), 256, 65536>>>(pc_b);          // 6
    squash_u_kernel<<<2304, 256>>>();

    for (int it = 0; it < 3; it++) {
        softmax_c_kernel<<<10, 256>>>();
        scale_w_kernel<<<5760, 256>>>(W_obj);
        gemm_kernel<0><<<dim3(8, 3), 256>>>((const float*)pu, (const float*)pwsc,
                                            (const float*)pz, (float*)ps, 512, 160, 9216);
        vsquash_kernel<<<20, 256>>>();
        if (it < 2) agree_kernel<<<1152, 320>>>(W_obj);
    }

    mask_kernel<<<512, 32>>>(out_obj, out_mask);
    h1_kernel<<<512, 512>>>(dec_w1, dec_b1);
    gemm_kernel<1><<<dim3(8, 16), 256>>>((const float*)ph1, dec_w2, dec_b2, (float*)ph2, 512, 1024, 512);
    gemm_kernel<2><<<dim3(8, 13), 256>>>((const float*)ph2, dec_w3, dec_b3, out_rec, 512, 784, 1024);
}